// round 2
// baseline (speedup 1.0000x reference)
#include <cuda_runtime.h>

// RadarSparseProcessor: out[v,o] = (sum_p sum_c x[v,p,c] * W[o,c]) / max(n_v, 1)
// V = 1048576, P = 4, C_IN = 4, C_OUT = 32
// voxel_num_points is INT32 (JAX x64 disabled downcasts the declared int64).
// Pure HBM-bound: ~196 MB traffic -> roofline ~25 us on GB300.

#define C_OUT 32
#define THREADS 256

__global__ __launch_bounds__(THREADS)
void radar_sparse_kernel(const float4* __restrict__ vf,   // [V*4] float4 (= [V,P=4,C_IN=4])
                         const float*  __restrict__ W,    // [32,4]
                         const int*    __restrict__ vnp,  // [V] int32
                         float4* __restrict__ out,        // [V*8] float4 (= [V,32])
                         int V)
{
    __shared__ float sW[C_OUT * 4];
    if (threadIdx.x < C_OUT * 4) sW[threadIdx.x] = W[threadIdx.x];
    __syncthreads();

    int v = blockIdx.x * blockDim.x + threadIdx.x;
    if (v >= V) return;

    // Load the 4 points (each a float4 of C_IN features) — 4x LDG.128, MLP=4
    const float4* vrow = vf + (size_t)v * 4;
    float4 p0 = vrow[0];
    float4 p1 = vrow[1];
    float4 p2 = vrow[2];
    float4 p3 = vrow[3];

    // Sum over points first (linearity): s[c] = sum_p x[v,p,c]
    float s0 = (p0.x + p1.x) + (p2.x + p3.x);
    float s1 = (p0.y + p1.y) + (p2.y + p3.y);
    float s2 = (p0.z + p1.z) + (p2.z + p3.z);
    float s3 = (p0.w + p1.w) + (p2.w + p3.w);

    int n = vnp[v];
    float inv = 1.0f / (float)(n > 1 ? n : 1);

    float4* orow = out + (size_t)v * 8;
    #pragma unroll
    for (int k = 0; k < 8; k++) {
        const float* w0 = &sW[(k * 4 + 0) * 4];
        const float* w1 = &sW[(k * 4 + 1) * 4];
        const float* w2 = &sW[(k * 4 + 2) * 4];
        const float* w3 = &sW[(k * 4 + 3) * 4];
        float4 o;
        o.x = (fmaf(w0[0], s0, fmaf(w0[1], s1, fmaf(w0[2], s2, w0[3] * s3)))) * inv;
        o.y = (fmaf(w1[0], s0, fmaf(w1[1], s1, fmaf(w1[2], s2, w1[3] * s3)))) * inv;
        o.z = (fmaf(w2[0], s0, fmaf(w2[1], s1, fmaf(w2[2], s2, w2[3] * s3)))) * inv;
        o.w = (fmaf(w3[0], s0, fmaf(w3[1], s1, fmaf(w3[2], s2, w3[3] * s3)))) * inv;
        orow[k] = o;
    }
}

extern "C" void kernel_launch(void* const* d_in, const int* in_sizes, int n_in,
                              void* d_out, int out_size)
{
    const float4* vf  = (const float4*)d_in[0];   // voxel_features [V,4,4] f32
    const float*  W   = (const float*)d_in[1];    // W [32,4] f32
    const int*    vnp = (const int*)d_in[2];      // voxel_num_points [V] i32
    float4*       out = (float4*)d_out;           // [V,32] f32

    int V = in_sizes[2];  // element count of voxel_num_points = V
    int blocks = (V + THREADS - 1) / THREADS;
    radar_sparse_kernel<<<blocks, THREADS>>>(vf, W, vnp, out, V);
}